// round 3
// baseline (speedup 1.0000x reference)
#include <cuda_runtime.h>

// ---------------- scratch (static device globals; no allocation) ----------------
__device__ float g_sig[64 * 4080];          // signature features, (64, 34*120) row-major
__device__ float g_hp[34 * 64 * 512];       // split-K partials of hidden layer

// ---------------- f32x2 packed helpers ----------------
__device__ __forceinline__ unsigned long long ffma2(unsigned long long a,
                                                    unsigned long long b,
                                                    unsigned long long c)
{
    unsigned long long d;
    asm("fma.rn.f32x2 %0, %1, %2, %3;" : "=l"(d) : "l"(a), "l"(b), "l"(c));
    return d;
}
__device__ __forceinline__ unsigned long long pack_dup(float x)
{
    unsigned long long d;
    asm("mov.b64 %0, {%1, %1};" : "=l"(d) : "f"(x));
    return d;
}

// ================= Kernel 1: depth-4 path signature =================
// 2176 paths (64 b x 34 vm). Block: 4 paths x 32 chunks = 128 threads, grid 544.
// Factored Chen step (183 FMA). All 128 chunk-sigs -> smem (62KB dyn), then
// element-parallel tree combine: every thread computes output channels.

__global__ void __launch_bounds__(128, 3) sig_kernel(const float* __restrict__ inp)
{
    extern __shared__ float sh[];            // 128 slots x 121 floats

    const int tid = threadIdx.x;
    const int pl = tid & 3;                  // path within block
    const int chunk = tid >> 2;              // 0..31
    const int pbase = blockIdx.x * 4;
    const int p = pbase + pl;
    const int b = p / 34;
    const int vm = p - b * 34;
    const float* base = inp + b * 30600 + vm;   // + c*10200 + t*34

    const int s0 = (chunk * 299) >> 5;
    const int s1 = ((chunk + 1) * 299) >> 5;

    float c1[3], c2[9], c3[27], c4[81];
#pragma unroll
    for (int i = 0; i < 3; i++) c1[i] = 0.f;
#pragma unroll
    for (int i = 0; i < 9; i++) c2[i] = 0.f;
#pragma unroll
    for (int i = 0; i < 27; i++) c3[i] = 0.f;
#pragma unroll
    for (int i = 0; i < 81; i++) c4[i] = 0.f;

    float xp[3], xc[3];
#pragma unroll
    for (int c = 0; c < 3; c++) xp[c] = __ldg(base + c * 10200 + s0 * 34);
#pragma unroll
    for (int c = 0; c < 3; c++) xc[c] = __ldg(base + c * 10200 + (s0 + 1) * 34);

    for (int s = s0; s < s1; ++s) {
        int tn = s + 2; if (tn > 299) tn = 299;
        float xn[3];
#pragma unroll
        for (int c = 0; c < 3; c++) xn[c] = __ldg(base + c * 10200 + tn * 34);

        float dx[3], dxh[3], dx3[3], e[3], bq[3], a[3];
#pragma unroll
        for (int i = 0; i < 3; i++) {
            dx[i]  = xc[i] - xp[i];
            dxh[i] = 0.5f * dx[i];
            dx3[i] = (1.0f / 3.0f) * dx[i];
            e[i]  = fmaf(0.25f, dx[i], c1[i]);
            bq[i] = c1[i] + dx3[i];
            a[i]  = c1[i] + dxh[i];
        }
        float q[9], sx[9];
#pragma unroll
        for (int i = 0; i < 3; i++)
#pragma unroll
            for (int j = 0; j < 3; j++) {
                q[i * 3 + j]  = fmaf(e[i],  dx3[j], c2[i * 3 + j]);
                sx[i * 3 + j] = fmaf(bq[i], dxh[j], c2[i * 3 + j]);
            }
        // level 4: c4 += (c3[ijk] + q[ij]*dxh[k]) * dx[l]
#pragma unroll
        for (int i = 0; i < 3; i++)
#pragma unroll
            for (int j = 0; j < 3; j++)
#pragma unroll
                for (int k = 0; k < 3; k++) {
                    const float r = fmaf(q[i * 3 + j], dxh[k], c3[i * 9 + j * 3 + k]);
                    const int x0 = i * 27 + j * 9 + k * 3;
#pragma unroll
                    for (int l = 0; l < 3; l++)
                        c4[x0 + l] = fmaf(r, dx[l], c4[x0 + l]);
                }
        // level 3
#pragma unroll
        for (int i = 0; i < 3; i++)
#pragma unroll
            for (int j = 0; j < 3; j++)
#pragma unroll
                for (int k = 0; k < 3; k++) {
                    const int x = i * 9 + j * 3 + k;
                    c3[x] = fmaf(sx[i * 3 + j], dx[k], c3[x]);
                }
        // level 2
#pragma unroll
        for (int i = 0; i < 3; i++)
#pragma unroll
            for (int j = 0; j < 3; j++)
                c2[i * 3 + j] = fmaf(a[i], dx[j], c2[i * 3 + j]);
        // level 1
#pragma unroll
        for (int i = 0; i < 3; i++) c1[i] += dx[i];

#pragma unroll
        for (int c = 0; c < 3; c++) { xp[c] = xc[c]; xc[c] = xn[c]; }
    }

    // ---- park this chunk's signature in its slot (slot index == tid) ----
    {
        float* w = sh + tid * 121;
#pragma unroll
        for (int i = 0; i < 3; i++) w[i] = c1[i];
#pragma unroll
        for (int i = 0; i < 9; i++) w[3 + i] = c2[i];
#pragma unroll
        for (int i = 0; i < 27; i++) w[12 + i] = c3[i];
#pragma unroll
        for (int i = 0; i < 81; i++) w[39 + i] = c4[i];
    }
    __syncthreads();

    // ---- element-parallel tree combine: 5 levels ----
    // slot(chunk, path) = chunk*4 + path. Pair (cA, cA+s); result -> cA slot.
#pragma unroll
    for (int d = 0; d < 5; d++) {
        const int s = 1 << d;
        const int nps = (16 >> d) * 4;                 // pair-slots this level
        const int tot4 = nps * 81;
        const int tot1 = nps * 39;
        const int IT4 = (tot4 + 127) / 128;
        const int IT1 = (tot1 + 127) / 128;

        float t123[20];
        // phase A1: compute L1-L3 outputs into registers (reads only; no writes)
#pragma unroll
        for (int it = 0; it < IT1; it++) {
            const int w = tid + it * 128;
            float r = 0.f;
            if (w < tot1) {
                const unsigned uw = (unsigned)w;
                const int ps = uw / 39u;
                const int e = w - ps * 39;
                const int pp = ps & 3, pr = ps >> 2;
                const float* A = sh + (((pr << (d + 1)) << 2) + pp) * 121;
                const float* B = A + (s << 2) * 121;
                if (e < 3) {
                    r = A[e] + B[e];
                } else if (e < 12) {
                    const int x = e - 3;
                    const int i = x / 3, j = x - (x / 3) * 3;
                    r = fmaf(A[i], B[j], A[e] + B[e]);
                } else {
                    const int x = e - 12;
                    const int ij = x / 3, k = x - ij * 3;
                    const int i = x / 9, jk = x - (x / 9) * 9;
                    r = fmaf(A[3 + ij], B[k],
                        fmaf(A[i], B[3 + jk], A[e] + B[e]));
                }
            }
            t123[it] = r;
        }
        // phase A2: compute + write L4 in place (writes A4 only; A4 read only by owner)
#pragma unroll
        for (int it = 0; it < IT4; it++) {
            const int w = tid + it * 128;
            if (w < tot4) {
                const unsigned uw = (unsigned)w;
                const int ps = uw / 81u;
                const int e = w - ps * 81;
                const int pp = ps & 3, pr = ps >> 2;
                float* A = sh + (((pr << (d + 1)) << 2) + pp) * 121;
                const float* B = A + (s << 2) * 121;
                const int q3 = e / 3;            // ijk
                const int l = e - q3 * 3;
                const int q9 = e / 9;            // ij
                const int kl = e - q9 * 9;
                const int i = e / 27;
                const int jkl = e - i * 27;
                float r = A[39 + e] + B[39 + e];
                r = fmaf(A[12 + q3], B[l], r);
                r = fmaf(A[3 + q9], B[3 + kl], r);
                r = fmaf(A[i], B[12 + jkl], r);
                A[39 + e] = r;
            }
        }
        __syncthreads();
        // phase B: commit L1-L3
#pragma unroll
        for (int it = 0; it < IT1; it++) {
            const int w = tid + it * 128;
            if (w < tot1) {
                const unsigned uw = (unsigned)w;
                const int ps = uw / 39u;
                const int e = w - ps * 39;
                const int pp = ps & 3, pr = ps >> 2;
                float* A = sh + (((pr << (d + 1)) << 2) + pp) * 121;
                A[e] = t123[it];
            }
        }
        __syncthreads();
    }

    // ---- final: slots 0..3 hold per-path signatures; coalesced store ----
    for (int idx = tid; idx < 480; idx += 128) {
        const int pp = idx / 120;
        const int r = idx - pp * 120;
        g_sig[pbase * 120 + idx] = sh[pp * 121 + r];
    }
}

// ================= Kernel 2: h-partials = sig @ W1^T (split-K 34) =================
// C (64 x 512). Grid (16 j-tiles of 32, 34 k-slices of 120), 128 thr.
// Tile 64x32, microtile 4x4, packed f32x2 FMA in the inner loop.

__global__ void __launch_bounds__(128) gemm1_kernel(const float* __restrict__ W1)
{
    __shared__ float As[8][68];
    __shared__ float Bs[8][36];

    const int jt = blockIdx.x;          // 0..15
    const int ks = blockIdx.y;          // 0..33
    const int tid = threadIdx.x;
    const int tx = tid & 7;             // 0..7  -> 4 cols each
    const int ty = tid >> 3;            // 0..15 -> 4 rows each
    const int k0 = ks * 120;
    const int j0 = jt * 32;

    const int lrow = tid >> 1;          // 0..63
    const int lk4 = (tid & 1) * 4;      // 0 or 4
    const float* Aptr = g_sig + lrow * 4080 + k0 + lk4;
    const float* Bptr = W1 + (j0 + (lrow & 31)) * 4080 + k0 + lk4;
    const bool bload = (tid < 64);

    unsigned long long accp[4][2];
#pragma unroll
    for (int r = 0; r < 4; r++) { accp[r][0] = 0ull; accp[r][1] = 0ull; }

    float4 av = *(const float4*)(Aptr);
    float4 bv = bload ? *(const float4*)(Bptr) : make_float4(0, 0, 0, 0);

    for (int kt = 0; kt < 120; kt += 8) {
        __syncthreads();
        As[lk4 + 0][lrow] = av.x; As[lk4 + 1][lrow] = av.y;
        As[lk4 + 2][lrow] = av.z; As[lk4 + 3][lrow] = av.w;
        if (bload) {
            Bs[lk4 + 0][lrow] = bv.x; Bs[lk4 + 1][lrow] = bv.y;
            Bs[lk4 + 2][lrow] = bv.z; Bs[lk4 + 3][lrow] = bv.w;
        }
        if (kt < 112) {
            av = *(const float4*)(Aptr + kt + 8);
            if (bload) bv = *(const float4*)(Bptr + kt + 8);
        }
        __syncthreads();
#pragma unroll
        for (int kk = 0; kk < 8; kk++) {
            const float4 a = *(const float4*)&As[kk][ty * 4];
            const ulonglong2 bp = *(const ulonglong2*)&Bs[kk][tx * 4];
            unsigned long long aa;
            aa = pack_dup(a.x);
            accp[0][0] = ffma2(aa, bp.x, accp[0][0]);
            accp[0][1] = ffma2(aa, bp.y, accp[0][1]);
            aa = pack_dup(a.y);
            accp[1][0] = ffma2(aa, bp.x, accp[1][0]);
            accp[1][1] = ffma2(aa, bp.y, accp[1][1]);
            aa = pack_dup(a.z);
            accp[2][0] = ffma2(aa, bp.x, accp[2][0]);
            accp[2][1] = ffma2(aa, bp.y, accp[2][1]);
            aa = pack_dup(a.w);
            accp[3][0] = ffma2(aa, bp.x, accp[3][0]);
            accp[3][1] = ffma2(aa, bp.y, accp[3][1]);
        }
    }

    float* outp = g_hp + ks * 32768 + j0;
#pragma unroll
    for (int r = 0; r < 4; r++) {
        const unsigned long long v0 = accp[r][0], v1 = accp[r][1];
        float4 v;
        v.x = __uint_as_float((unsigned)(v0 & 0xffffffffu));
        v.y = __uint_as_float((unsigned)(v0 >> 32));
        v.z = __uint_as_float((unsigned)(v1 & 0xffffffffu));
        v.w = __uint_as_float((unsigned)(v1 >> 32));
        *(float4*)(outp + (ty * 4 + r) * 512 + tx * 4) = v;
    }
}

// ====== Kernel 3: out = (sum_s hp_s + b1) @ W2^T + b2, grid (64 rows, 5 j-tiles) ======

__global__ void __launch_bounds__(256) gemm2_kernel(const float* __restrict__ b1,
                                                    const float* __restrict__ W2,
                                                    const float* __restrict__ b2,
                                                    float* __restrict__ out)
{
    __shared__ float hs[512];
    const int i = blockIdx.x;
    const int jt = blockIdx.y;
    const int tid = threadIdx.x;

    for (int k = tid; k < 512; k += 256) {
        float v0 = b1[k], v1 = 0.f;
        const float* hp = g_hp + i * 512 + k;
#pragma unroll
        for (int s = 0; s < 34; s += 2) {
            v0 += hp[s * 32768];
            v1 += hp[(s + 1) * 32768];
        }
        hs[k] = v0 + v1;
    }
    __syncthreads();

    const int jl = tid >> 3;            // 0..31
    const int ell = tid & 7;            // 0..7
    if (jl < 31) {
        const int j = jt * 31 + jl;     // <= 154
        const float4* w = (const float4*)(W2 + j * 512) + ell;
        float acc0 = 0.f, acc1 = 0.f;
#pragma unroll
        for (int it = 0; it < 16; it += 2) {
            const float4 w0 = w[it * 8];
            const float4 w1 = w[(it + 1) * 8];
            const float* h0 = &hs[(ell + it * 8) * 4];
            const float* h1 = &hs[(ell + (it + 1) * 8) * 4];
            acc0 = fmaf(h0[0], w0.x, acc0); acc0 = fmaf(h0[1], w0.y, acc0);
            acc0 = fmaf(h0[2], w0.z, acc0); acc0 = fmaf(h0[3], w0.w, acc0);
            acc1 = fmaf(h1[0], w1.x, acc1); acc1 = fmaf(h1[1], w1.y, acc1);
            acc1 = fmaf(h1[2], w1.z, acc1); acc1 = fmaf(h1[3], w1.w, acc1);
        }
        float acc = acc0 + acc1;
#pragma unroll
        for (int m = 1; m < 8; m <<= 1)
            acc += __shfl_xor_sync(0xffffffffu, acc, m);
        if (ell == 0) out[i * 155 + j] = acc + b2[j];
    }
}

// ================================ launch =================================

extern "C" void kernel_launch(void* const* d_in, const int* in_sizes, int n_in,
                              void* d_out, int out_size)
{
    const float* inp = (const float*)d_in[0];
    const float* W1  = (const float*)d_in[1];
    const float* b1  = (const float*)d_in[2];
    const float* W2  = (const float*)d_in[3];
    const float* b2  = (const float*)d_in[4];
    float* out = (float*)d_out;

    const int sig_smem = 128 * 121 * (int)sizeof(float);   // 61952 B
    static int smem_set = 0;
    if (!smem_set) {
        cudaFuncSetAttribute(sig_kernel,
                             cudaFuncAttributeMaxDynamicSharedMemorySize, sig_smem);
        smem_set = 1;
    }

    sig_kernel<<<544, 128, sig_smem>>>(inp);
    gemm1_kernel<<<dim3(16, 34), 128>>>(W1);
    gemm2_kernel<<<dim3(64, 5), 256>>>(b1, W2, b2, out);
}

// round 4
// speedup vs baseline: 1.1786x; 1.1786x over previous
#include <cuda_runtime.h>

// ---------------- scratch (static device globals; no allocation) ----------------
__device__ float g_sig[64 * 4080];          // signature features, (64, 34*120) row-major
__device__ float g_hp[34 * 64 * 512];       // split-K partials of hidden layer

// ---------------- f32x2 packed helpers ----------------
__device__ __forceinline__ unsigned long long ffma2(unsigned long long a,
                                                    unsigned long long b,
                                                    unsigned long long c)
{
    unsigned long long d;
    asm("fma.rn.f32x2 %0, %1, %2, %3;" : "=l"(d) : "l"(a), "l"(b), "l"(c));
    return d;
}
__device__ __forceinline__ unsigned long long pack_dup(float x)
{
    unsigned long long d;
    asm("mov.b64 %0, {%1, %1};" : "=l"(d) : "f"(x));
    return d;
}

// ================= Kernel 1: depth-4 path signature =================
// 2176 paths (64 b x 34 vm). Block: 4 paths x 32 chunks = 128 threads, grid 544.
// Scan: factored Chen step (183 FMA), direct __ldg with 1-step prefetch.
// Combine: 5 levels; each merged segment's 120 channels split across its
// 2^(d+1) owner threads via nested bit-reversed ranges. c4 updated in place
// in the A-lineage slot; L1-3 ping-pong P<->Q. ONE barrier per level.

__global__ void __launch_bounds__(128, 3) sig_kernel(const float* __restrict__ inp)
{
    extern __shared__ float sh[];
    float* P = sh;                       // 128 slots x 121 floats (L1-3 at [0,39), c4 at [39,120))
    float* Q = sh + 128 * 121;           // 64 slots x 41 floats (L1-3 ping)

    const int tid = threadIdx.x;
    const int pl = tid & 3;              // path within block
    const int chunk = tid >> 2;          // 0..31
    const int pbase = blockIdx.x * 4;
    const int p = pbase + pl;
    const int b = p / 34;
    const int vm = p - b * 34;
    const float* base = inp + b * 30600 + vm;   // + c*10200 + t*34

    const int s0 = (chunk * 299) >> 5;
    const int s1 = ((chunk + 1) * 299) >> 5;

    float c1[3], c2[9], c3[27], c4[81];
#pragma unroll
    for (int i = 0; i < 3; i++) c1[i] = 0.f;
#pragma unroll
    for (int i = 0; i < 9; i++) c2[i] = 0.f;
#pragma unroll
    for (int i = 0; i < 27; i++) c3[i] = 0.f;
#pragma unroll
    for (int i = 0; i < 81; i++) c4[i] = 0.f;

    float xp[3], xc[3];
#pragma unroll
    for (int c = 0; c < 3; c++) xp[c] = __ldg(base + c * 10200 + s0 * 34);
#pragma unroll
    for (int c = 0; c < 3; c++) xc[c] = __ldg(base + c * 10200 + (s0 + 1) * 34);

    for (int s = s0; s < s1; ++s) {
        int tn = s + 2; if (tn > 299) tn = 299;
        float xn[3];
#pragma unroll
        for (int c = 0; c < 3; c++) xn[c] = __ldg(base + c * 10200 + tn * 34);

        float dx[3], dxh[3], dx3[3], e[3], bq[3], a[3];
#pragma unroll
        for (int i = 0; i < 3; i++) {
            dx[i]  = xc[i] - xp[i];
            dxh[i] = 0.5f * dx[i];
            dx3[i] = (1.0f / 3.0f) * dx[i];
            e[i]  = fmaf(0.25f, dx[i], c1[i]);
            bq[i] = c1[i] + dx3[i];
            a[i]  = c1[i] + dxh[i];
        }
        float q[9], sx[9];
#pragma unroll
        for (int i = 0; i < 3; i++)
#pragma unroll
            for (int j = 0; j < 3; j++) {
                q[i * 3 + j]  = fmaf(e[i],  dx3[j], c2[i * 3 + j]);
                sx[i * 3 + j] = fmaf(bq[i], dxh[j], c2[i * 3 + j]);
            }
#pragma unroll
        for (int i = 0; i < 3; i++)
#pragma unroll
            for (int j = 0; j < 3; j++)
#pragma unroll
                for (int k = 0; k < 3; k++) {
                    const float r = fmaf(q[i * 3 + j], dxh[k], c3[i * 9 + j * 3 + k]);
                    const int x0 = i * 27 + j * 9 + k * 3;
#pragma unroll
                    for (int l = 0; l < 3; l++)
                        c4[x0 + l] = fmaf(r, dx[l], c4[x0 + l]);
                }
#pragma unroll
        for (int i = 0; i < 3; i++)
#pragma unroll
            for (int j = 0; j < 3; j++)
#pragma unroll
                for (int k = 0; k < 3; k++) {
                    const int x = i * 9 + j * 3 + k;
                    c3[x] = fmaf(sx[i * 3 + j], dx[k], c3[x]);
                }
#pragma unroll
        for (int i = 0; i < 3; i++)
#pragma unroll
            for (int j = 0; j < 3; j++)
                c2[i * 3 + j] = fmaf(a[i], dx[j], c2[i * 3 + j]);
#pragma unroll
        for (int i = 0; i < 3; i++) c1[i] += dx[i];

#pragma unroll
        for (int c = 0; c < 3; c++) { xp[c] = xc[c]; xc[c] = xn[c]; }
    }

    // ---- park chunk signature into P slot (slot id == tid) ----
    {
        float* w = P + tid * 121;
#pragma unroll
        for (int i = 0; i < 3; i++) w[i] = c1[i];
#pragma unroll
        for (int i = 0; i < 9; i++) w[3 + i] = c2[i];
#pragma unroll
        for (int i = 0; i < 27; i++) w[12 + i] = c3[i];
#pragma unroll
        for (int i = 0; i < 81; i++) w[39 + i] = c4[i];
    }
    __syncthreads();

    // ---- 5-level distributed tree combine, 1 barrier/level ----
    int idx = 0;
#pragma unroll
    for (int d = 0; d < 5; d++) {
        idx = (idx << 1) | ((chunk >> d) & 1);
        const int aseg = (chunk >> (d + 1)) << 1;     // units of 2^d chunks
        const float* A13;
        const float* B13;
        float* dst;
        if ((d & 1) == 0) {                           // src P, dst Q
            A13 = P + ((aseg << d) * 4 + pl) * 121;
            B13 = P + (((aseg + 1) << d) * 4 + pl) * 121;
            dst = Q + ((aseg >> 1) * 4 + pl) * 41;
        } else {                                      // src Q, dst P
            A13 = Q + (aseg * 4 + pl) * 41;
            B13 = Q + ((aseg + 1) * 4 + pl) * 41;
            dst = P + (((aseg >> 1) << (d + 1)) * 4 + pl) * 121;
        }
        float* C4A = P + ((aseg << d) * 4 + pl) * 121 + 39;
        const float* C4B = P + (((aseg + 1) << d) * 4 + pl) * 121 + 39;

        const int gsh = d + 1;
        const int lo1 = (39 * idx) >> gsh, hi1 = (39 * (idx + 1)) >> gsh;
        const int lo4 = (81 * idx) >> gsh, hi4 = (81 * (idx + 1)) >> gsh;

        for (int e = lo1; e < hi1; e++) {             // L1-3 of merged segment
            float v = A13[e] + B13[e];
            if (e >= 12) {
                const int x = e - 12;
                const int ij = (x * 86) >> 8, k = x - 3 * ij;
                const int i2 = (x * 57) >> 9, jk = x - 9 * i2;
                v = fmaf(A13[3 + ij], B13[k], fmaf(A13[i2], B13[3 + jk], v));
            } else if (e >= 3) {
                const int x = e - 3;
                const int i2 = (x * 86) >> 8, j = x - 3 * i2;
                v = fmaf(A13[i2], B13[j], v);
            }
            dst[e] = v;
        }
        for (int e = lo4; e < hi4; e++) {             // L4, in place into A slot
            const int q3 = (e * 86) >> 8, l = e - 3 * q3;
            const int q9 = (e * 57) >> 9, kl = e - 9 * q9;
            const int i2 = (e * 19) >> 9, jkl = e - 27 * i2;
            float r = C4A[e] + C4B[e];
            r = fmaf(A13[12 + q3], B13[l], r);
            r = fmaf(A13[3 + q9],  B13[3 + kl], r);
            r = fmaf(A13[i2],      B13[12 + jkl], r);
            C4A[e] = r;
        }
        __syncthreads();
    }

    // ---- final: L1-3 in Q slot pl, c4 in P slot pl; coalesced store ----
    for (int it = 0; it < 4; it++) {
        const int idx2 = tid + it * 128;
        if (idx2 < 480) {
            const int pp = (idx2 * 547) >> 16;        // idx2 / 120
            const int r = idx2 - pp * 120;
            const float v = (r < 39) ? Q[pp * 41 + r] : P[pp * 121 + r];
            g_sig[pbase * 120 + idx2] = v;
        }
    }
}

// ================= Kernel 2: h-partials = sig @ W1^T (split-K 34) =================

__global__ void __launch_bounds__(128) gemm1_kernel(const float* __restrict__ W1)
{
    __shared__ float As[8][68];
    __shared__ float Bs[8][36];

    const int jt = blockIdx.x;          // 0..15
    const int ks = blockIdx.y;          // 0..33
    const int tid = threadIdx.x;
    const int tx = tid & 7;
    const int ty = tid >> 3;
    const int k0 = ks * 120;
    const int j0 = jt * 32;

    const int lrow = tid >> 1;          // 0..63
    const int lk4 = (tid & 1) * 4;      // 0 or 4
    const float* Aptr = g_sig + lrow * 4080 + k0 + lk4;
    const float* Bptr = W1 + (j0 + (lrow & 31)) * 4080 + k0 + lk4;
    const bool bload = (tid < 64);

    unsigned long long accp[4][2];
#pragma unroll
    for (int r = 0; r < 4; r++) { accp[r][0] = 0ull; accp[r][1] = 0ull; }

    float4 av = *(const float4*)(Aptr);
    float4 bv = bload ? *(const float4*)(Bptr) : make_float4(0, 0, 0, 0);

    for (int kt = 0; kt < 120; kt += 8) {
        __syncthreads();
        As[lk4 + 0][lrow] = av.x; As[lk4 + 1][lrow] = av.y;
        As[lk4 + 2][lrow] = av.z; As[lk4 + 3][lrow] = av.w;
        if (bload) {
            Bs[lk4 + 0][lrow] = bv.x; Bs[lk4 + 1][lrow] = bv.y;
            Bs[lk4 + 2][lrow] = bv.z; Bs[lk4 + 3][lrow] = bv.w;
        }
        if (kt < 112) {
            av = *(const float4*)(Aptr + kt + 8);
            if (bload) bv = *(const float4*)(Bptr + kt + 8);
        }
        __syncthreads();
#pragma unroll
        for (int kk = 0; kk < 8; kk++) {
            const float4 a = *(const float4*)&As[kk][ty * 4];
            const ulonglong2 bp = *(const ulonglong2*)&Bs[kk][tx * 4];
            unsigned long long aa;
            aa = pack_dup(a.x);
            accp[0][0] = ffma2(aa, bp.x, accp[0][0]);
            accp[0][1] = ffma2(aa, bp.y, accp[0][1]);
            aa = pack_dup(a.y);
            accp[1][0] = ffma2(aa, bp.x, accp[1][0]);
            accp[1][1] = ffma2(aa, bp.y, accp[1][1]);
            aa = pack_dup(a.z);
            accp[2][0] = ffma2(aa, bp.x, accp[2][0]);
            accp[2][1] = ffma2(aa, bp.y, accp[2][1]);
            aa = pack_dup(a.w);
            accp[3][0] = ffma2(aa, bp.x, accp[3][0]);
            accp[3][1] = ffma2(aa, bp.y, accp[3][1]);
        }
    }

    float* outp = g_hp + ks * 32768 + j0;
#pragma unroll
    for (int r = 0; r < 4; r++) {
        const unsigned long long v0 = accp[r][0], v1 = accp[r][1];
        float4 v;
        v.x = __uint_as_float((unsigned)(v0 & 0xffffffffu));
        v.y = __uint_as_float((unsigned)(v0 >> 32));
        v.z = __uint_as_float((unsigned)(v1 & 0xffffffffu));
        v.w = __uint_as_float((unsigned)(v1 >> 32));
        *(float4*)(outp + (ty * 4 + r) * 512 + tx * 4) = v;
    }
}

// ====== Kernel 3: out = (sum_s hp_s + b1) @ W2^T + b2, grid (64 rows, 5 j-tiles) ======

__global__ void __launch_bounds__(256) gemm2_kernel(const float* __restrict__ b1,
                                                    const float* __restrict__ W2,
                                                    const float* __restrict__ b2,
                                                    float* __restrict__ out)
{
    __shared__ float hs[512];
    const int i = blockIdx.x;
    const int jt = blockIdx.y;
    const int tid = threadIdx.x;

    for (int k = tid; k < 512; k += 256) {
        float v0 = b1[k], v1 = 0.f;
        const float* hp = g_hp + i * 512 + k;
#pragma unroll
        for (int s = 0; s < 34; s += 2) {
            v0 += hp[s * 32768];
            v1 += hp[(s + 1) * 32768];
        }
        hs[k] = v0 + v1;
    }
    __syncthreads();

    const int jl = tid >> 3;
    const int ell = tid & 7;
    if (jl < 31) {
        const int j = jt * 31 + jl;
        const float4* w = (const float4*)(W2 + j * 512) + ell;
        float acc0 = 0.f, acc1 = 0.f;
#pragma unroll
        for (int it = 0; it < 16; it += 2) {
            const float4 w0 = w[it * 8];
            const float4 w1 = w[(it + 1) * 8];
            const float* h0 = &hs[(ell + it * 8) * 4];
            const float* h1 = &hs[(ell + (it + 1) * 8) * 4];
            acc0 = fmaf(h0[0], w0.x, acc0); acc0 = fmaf(h0[1], w0.y, acc0);
            acc0 = fmaf(h0[2], w0.z, acc0); acc0 = fmaf(h0[3], w0.w, acc0);
            acc1 = fmaf(h1[0], w1.x, acc1); acc1 = fmaf(h1[1], w1.y, acc1);
            acc1 = fmaf(h1[2], w1.z, acc1); acc1 = fmaf(h1[3], w1.w, acc1);
        }
        float acc = acc0 + acc1;
#pragma unroll
        for (int m = 1; m < 8; m <<= 1)
            acc += __shfl_xor_sync(0xffffffffu, acc, m);
        if (ell == 0) out[i * 155 + j] = acc + b2[j];
    }
}

// ================================ launch =================================

extern "C" void kernel_launch(void* const* d_in, const int* in_sizes, int n_in,
                              void* d_out, int out_size)
{
    const float* inp = (const float*)d_in[0];
    const float* W1  = (const float*)d_in[1];
    const float* b1  = (const float*)d_in[2];
    const float* W2  = (const float*)d_in[3];
    const float* b2  = (const float*)d_in[4];
    float* out = (float*)d_out;

    const int sig_smem = (128 * 121 + 64 * 41) * (int)sizeof(float);   // 72448 B
    static int smem_set = 0;
    if (!smem_set) {
        cudaFuncSetAttribute(sig_kernel,
                             cudaFuncAttributeMaxDynamicSharedMemorySize, sig_smem);
        smem_set = 1;
    }

    sig_kernel<<<544, 128, sig_smem>>>(inp);
    gemm1_kernel<<<dim3(16, 34), 128>>>(W1);
    gemm2_kernel<<<dim3(64, 5), 256>>>(b1, W2, b2, out);
}